// round 11
// baseline (speedup 1.0000x reference)
#include <cuda_runtime.h>
#include <cuda_fp16.h>
#include <math_constants.h>
#include <cstdint>
#include <cstring>

#define N 4096
#define D 128
#define NT 512
#define Q 8
#define NCOL 8192
#define INV_TEMP 20.0f
#define EX2_SCALE 28.85390081777927f   // 20 * log2(e)
#define TILE_BYTES 32768
#define NUM_CTA 296
#define NUM_RB 32
#define CT_PER_RB 64

// ---------------------------------------------------------------------------
// Device scratch (no allocation allowed)
// ---------------------------------------------------------------------------
__device__ float  g_num[N];
__device__ float  g_lognum[N];
__device__ float  g_den[N];
__device__ double g_lossp[256];
__device__ unsigned g_kc_done;          // self-resetting last-block ticket
__device__ int      g_tick[NUM_RB];     // per-rb unit tickets (reset by last CTA)
__device__ unsigned g_done;             // kB finish counter (wraps to 0)
// concat(yf, x) fp16, TILE-MAJOR SWIZZLED: tile tl = bytes [tl*32768,(tl+1)*32768)
// element (row r, 16B-unit c8): off = r*256 + ((c8 ^ (r&7)) << 4)
__device__ __align__(128) __half g_Bh[NCOL * D];
// x rows prescaled by EX2_SCALE (A/row operand only), same tiled layout, 32 tiles
__device__ __align__(128) __half g_Ah[N * D];

// ---------------------------------------------------------------------------
// Helpers (base ISA; cp.async.bulk/mbarrier are sm_90 base features)
// ---------------------------------------------------------------------------
__device__ __forceinline__ uint32_t smem_u32(const void* p) {
    uint32_t a;
    asm("{ .reg .u64 t; cvta.to.shared.u64 t, %1; cvt.u32.u64 %0, t; }"
        : "=r"(a) : "l"(p));
    return a;
}
__device__ __forceinline__ void mbar_init(uint32_t addr, uint32_t cnt) {
    asm volatile("mbarrier.init.shared.b64 [%0], %1;" :: "r"(addr), "r"(cnt) : "memory");
}
__device__ __forceinline__ void mbar_expect_tx(uint32_t addr, uint32_t tx) {
    asm volatile("mbarrier.arrive.expect_tx.shared.b64 _, [%0], %1;"
                 :: "r"(addr), "r"(tx) : "memory");
}
__device__ __forceinline__ void mbar_wait(uint32_t addr, uint32_t parity) {
    asm volatile(
        "{\n\t.reg .pred P;\n\t"
        "LW_%=:\n\t"
        "mbarrier.try_wait.parity.shared.b64 P, [%0], %1;\n\t"
        "@P bra LD_%=;\n\t"
        "bra LW_%=;\n\t"
        "LD_%=:\n\t}"
        :: "r"(addr), "r"(parity) : "memory");
}
__device__ __forceinline__ void bulk_g2s(uint32_t dst, const void* src,
                                         uint32_t bytes, uint32_t mbar) {
    asm volatile(
        "cp.async.bulk.shared::cluster.global.mbarrier::complete_tx::bytes "
        "[%0], [%1], %2, [%3];"
        :: "r"(dst), "l"(src), "r"(bytes), "r"(mbar) : "memory");
}
__device__ __forceinline__ void ldsm4(uint32_t* v, uint32_t addr) {
    asm volatile("ldmatrix.sync.aligned.m8n8.x4.shared.b16 {%0,%1,%2,%3}, [%4];"
                 : "=r"(v[0]), "=r"(v[1]), "=r"(v[2]), "=r"(v[3]) : "r"(addr));
}
__device__ __forceinline__ void mma16816(float* c, const uint32_t* a, const uint32_t* b) {
    asm volatile(
        "mma.sync.aligned.m16n8k16.row.col.f32.f16.f16.f32 "
        "{%0,%1,%2,%3}, {%4,%5,%6,%7}, {%8,%9}, {%0,%1,%2,%3};"
        : "+f"(c[0]), "+f"(c[1]), "+f"(c[2]), "+f"(c[3])
        : "r"(a[0]), "r"(a[1]), "r"(a[2]), "r"(a[3]), "r"(b[0]), "r"(b[1]));
}
__device__ __forceinline__ float ex2f(float x) {
    float r;
    asm("ex2.approx.f32 %0, %1;" : "=f"(r) : "f"(x));
    return r;
}

// ---------------------------------------------------------------------------
// SMEM layout for kB (per CTA; 2 CTAs/SM)
// ---------------------------------------------------------------------------
#define SM_A    0                   // 32768
#define SM_B0   32768               // + buf*32768 (B1 at 65536)
#define SM_CTS  98304               // int cts[2][128] = 1024
#define SM_RED  99328               // float red[128][2] = 1024
#define SM_CTRL 100352              // int ctrl[2]
#define SM_MBAR 100368              // 3 mbarriers (A, B0, B1)
#define SMEM_BYTES 100480

// ---------------------------------------------------------------------------
// K1: fused prep.
//   blocks [0, 512):    convert concat(yf, x) -> fp16 tiled/swizzled (+ scaled A copy)
//   blocks [512, 1024): per-row sim_p/num/lognum (exact fp32), zero g_den
// ---------------------------------------------------------------------------
__global__ void K1(const float* __restrict__ x,
                   const int*   __restrict__ tidx,
                   const float* __restrict__ y) {
    int bid = blockIdx.x;
    int tid = threadIdx.x;
    if (bid < 512) {
        int uid = bid * 256 + tid;          // 131072 16B-units
        int R   = uid >> 4;                 // concat row
        int c8  = uid & 15;
        int tl  = R >> 7;
        int r   = R & 127;
        const float4* rowp = (R < N) ? ((const float4*)y + (size_t)R * (D / 4))
                                     : ((const float4*)x + (size_t)(R - N) * (D / 4));
        float4 f0 = rowp[c8 * 2];
        float4 f1 = rowp[c8 * 2 + 1];
        uint32_t off = (uint32_t)r * 256 + ((uint32_t)(c8 ^ (r & 7)) << 4);
        {
            __half2 hh[4];
            hh[0] = __floats2half2_rn(f0.x, f0.y);
            hh[1] = __floats2half2_rn(f0.z, f0.w);
            hh[2] = __floats2half2_rn(f1.x, f1.y);
            hh[3] = __floats2half2_rn(f1.z, f1.w);
            uint4 o; memcpy(&o, hh, 16);
            *(uint4*)((char*)g_Bh + (uint32_t)tl * TILE_BYTES + off) = o;
        }
        if (R >= N) {                       // prescaled A copy (x rows only)
            __half2 hs[4];
            hs[0] = __floats2half2_rn(f0.x * EX2_SCALE, f0.y * EX2_SCALE);
            hs[1] = __floats2half2_rn(f0.z * EX2_SCALE, f0.w * EX2_SCALE);
            hs[2] = __floats2half2_rn(f1.x * EX2_SCALE, f1.y * EX2_SCALE);
            hs[3] = __floats2half2_rn(f1.z * EX2_SCALE, f1.w * EX2_SCALE);
            uint4 o; memcpy(&o, hs, 16);
            *(uint4*)((char*)g_Ah + (uint32_t)(tl - 32) * TILE_BYTES + off) = o;
        }
    } else {
        int gw   = (bid - 512) * 8 + (tid >> 5);
        int lane = tid & 31;
        const float* xr = x + (size_t)gw * D;
        float x0 = xr[lane], x1 = xr[lane + 32], x2 = xr[lane + 64], x3 = xr[lane + 96];
        const float* yb = y + (size_t)tidx[gw] * Q * D;
        float mn = CUDART_INF_F;
#pragma unroll
        for (int q = 0; q < Q; q++) {
            const float* yr = yb + q * D;
            float s = x0 * yr[lane] + x1 * yr[lane + 32]
                    + x2 * yr[lane + 64] + x3 * yr[lane + 96];
#pragma unroll
            for (int o = 16; o > 0; o >>= 1) s += __shfl_xor_sync(0xffffffffu, s, o);
            mn = fminf(mn, s);
        }
        if (lane == 0) {
            float lognum = mn * INV_TEMP;
            g_num[gw]    = __expf(lognum);
            g_lognum[gw] = lognum;
            g_den[gw]    = 0.0f;
        }
    }
}

// ---------------------------------------------------------------------------
// kB: persistent ticket-scheduled fp16 masked-exp GEMM row-sum.
//   296 resident CTAs; 2048 units (rb 0..31, ct 0..63); per-rb tickets with
//   home-rb anchoring (A tile mostly resident). B double-buffered + prefetch.
// ---------------------------------------------------------------------------
__global__ __launch_bounds__(256, 2)
void kB(const int* __restrict__ tidx) {
    extern __shared__ char smem[];
    const uint32_t sb = smem_u32(smem);
    const int tid  = threadIdx.x;
    const int lane = tid & 31;
    const int wrp  = tid >> 5;
    const int wy   = wrp >> 1;            // 0..3  (32-row slab)
    const int wx   = wrp & 1;             // 0..1  (64-col slab)

    int*   cts  = (int*)  (smem + SM_CTS);
    float* red  = (float*)(smem + SM_RED);
    int*   ctrl = (int*)  (smem + SM_CTRL);
    const uint32_t mbA  = sb + SM_MBAR;
    const uint32_t mbB0 = sb + SM_MBAR + 8;
    const uint32_t mbB1 = sb + SM_MBAR + 16;
    const char* gB = (const char*)g_Bh;
    const char* gA = (const char*)g_Ah;

    if (tid == 0) { mbar_init(mbA, 1); mbar_init(mbB0, 1); mbar_init(mbB1, 1); }

    // ldmatrix per-lane address precompute (rb/ct independent)
    const int lr = lane & 7, g = lane >> 3;
    uint32_t arow[2], ars[2], brow[4], brs[4];
#pragma unroll
    for (int mt = 0; mt < 2; mt++) {
        int r = wy * 32 + mt * 16 + (g & 1) * 8 + lr;
        arow[mt] = (uint32_t)(r * 256); ars[mt] = (uint32_t)(r & 7);
    }
    const uint32_t akb = (uint32_t)(g >> 1);
#pragma unroll
    for (int np = 0; np < 4; np++) {
        int r = wx * 64 + np * 16 + (g >> 1) * 8 + lr;
        brow[np] = (uint32_t)(r * 256); brs[np] = (uint32_t)(r & 7);
    }
    const uint32_t bkb = (uint32_t)(g & 1);

    // ---- ticket state (tid 0 only meaningful) ----
    int rot = 0;
    int start_rb = (int)(((unsigned)blockIdx.x * NUM_RB) / NUM_CTA);
    auto acq = [&]() -> int {
        while (rot < NUM_RB) {
            int rb = start_rb + rot; if (rb >= NUM_RB) rb -= NUM_RB;
            int t = atomicAdd(&g_tick[rb], 1);
            if (t < CT_PER_RB) return rb * CT_PER_RB + t;
            rot++;
        }
        return -1;
    };

    // ---- prologue: acquire first two units, start loads ----
    if (tid == 0) ctrl[0] = acq();
    __syncthreads();
    int cur = ctrl[0];
    int loadedA = -1;
    int cA = 0, cB0 = 0, cB1 = 0;
    bool A_pending = false;
    int buf = 0;
    if (cur >= 0) {
        int rb = cur >> 6, ct = cur & 63;
        if (tid == 0) {
            mbar_expect_tx(mbA, TILE_BYTES);
            bulk_g2s(sb + SM_A, gA + (size_t)rb * TILE_BYTES, TILE_BYTES, mbA);
            mbar_expect_tx(mbB0, TILE_BYTES);
            bulk_g2s(sb + SM_B0, gB + (size_t)ct * TILE_BYTES, TILE_BYTES, mbB0);
        }
        if (ct >= 32 && tid < 128) cts[tid] = __ldg(&tidx[ct * 128 + tid - N]);
        loadedA = rb;
        A_pending = true;
    }
    if (tid == 0) ctrl[1] = (cur >= 0) ? acq() : -1;
    __syncthreads();
    int nxt = ctrl[1];

    while (cur >= 0) {
        const int rb = cur >> 6, ct = cur & 63;
        const bool pre = (nxt >= 0) && ((nxt >> 6) == loadedA);
        if (pre) {
            int nct = nxt & 63;
            if (tid == 0) {
                uint32_t mb = buf ? mbB0 : mbB1;
                mbar_expect_tx(mb, TILE_BYTES);
                bulk_g2s(sb + SM_B0 + (uint32_t)(buf ^ 1) * TILE_BYTES,
                         gB + (size_t)nct * TILE_BYTES, TILE_BYTES, mb);
            }
            if (nct >= 32 && tid < 128)
                cts[(buf ^ 1) * 128 + tid] = __ldg(&tidx[nct * 128 + tid - N]);
        }
        if (A_pending) { mbar_wait(mbA, (uint32_t)(cA & 1)); cA++; A_pending = false; }
        if (buf == 0) { mbar_wait(mbB0, (uint32_t)(cB0 & 1)); cB0++; }
        else          { mbar_wait(mbB1, (uint32_t)(cB1 & 1)); cB1++; }
        __syncthreads();

        // row tracks for this unit
        int rtk[2][2];
#pragma unroll
        for (int mt = 0; mt < 2; mt++)
#pragma unroll
            for (int h = 0; h < 2; h++) {
                int rl = wy * 32 + mt * 16 + (lane >> 2) + h * 8;
                rtk[mt][h] = __ldg(&tidx[rb * 128 + rl]);
            }

        // ---- compute 128x128 tile (A prescaled -> acc = 28.85*S) ----
        float acc[2][8][4];
#pragma unroll
        for (int mt = 0; mt < 2; mt++)
#pragma unroll
            for (int nt = 0; nt < 8; nt++)
#pragma unroll
                for (int e = 0; e < 4; e++) acc[mt][nt][e] = 0.f;

        const uint32_t bcur = sb + SM_B0 + (uint32_t)buf * TILE_BYTES;
#pragma unroll
        for (int ks = 0; ks < 8; ks++) {
            uint32_t af[2][4];
#pragma unroll
            for (int mt = 0; mt < 2; mt++)
                ldsm4(af[mt], sb + SM_A + arow[mt]
                      + ((((uint32_t)(ks * 2) + akb) ^ ars[mt]) << 4));
            uint32_t bf[4][4];
#pragma unroll
            for (int np = 0; np < 4; np++)
                ldsm4(bf[np], bcur + brow[np]
                      + ((((uint32_t)(ks * 2) + bkb) ^ brs[np]) << 4));
#pragma unroll
            for (int mt = 0; mt < 2; mt++)
#pragma unroll
                for (int nt = 0; nt < 8; nt++)
                    mma16816(acc[mt][nt], af[mt], &bf[nt >> 1][(nt & 1) * 2]);
        }

        // ---- epilogue: mask same-track, ex2, per-row partials ----
        float rs[2][2] = {{0.f, 0.f}, {0.f, 0.f}};
        if (ct < 32) {
            int vbase = (ct * 128 + wx * 64 + (lane & 3) * 2) >> 3;
#pragma unroll
            for (int mt = 0; mt < 2; mt++)
#pragma unroll
                for (int nt = 0; nt < 8; nt++) {
                    int trk = vbase + nt;
                    float s01 = ex2f(acc[mt][nt][0]) + ex2f(acc[mt][nt][1]);
                    float s23 = ex2f(acc[mt][nt][2]) + ex2f(acc[mt][nt][3]);
                    if (trk != rtk[mt][0]) rs[mt][0] += s01;
                    if (trk != rtk[mt][1]) rs[mt][1] += s23;
                }
        } else {
            const int* ctc = cts + buf * 128;
#pragma unroll
            for (int mt = 0; mt < 2; mt++)
#pragma unroll
                for (int nt = 0; nt < 8; nt++) {
                    int colb = wx * 64 + nt * 8 + (lane & 3) * 2;
                    int c0t = ctc[colb], c1t = ctc[colb + 1];
                    float e0 = ex2f(acc[mt][nt][0]);
                    float e1 = ex2f(acc[mt][nt][1]);
                    float e2 = ex2f(acc[mt][nt][2]);
                    float e3 = ex2f(acc[mt][nt][3]);
                    if (c0t != rtk[mt][0]) rs[mt][0] += e0;
                    if (c1t != rtk[mt][0]) rs[mt][0] += e1;
                    if (c0t != rtk[mt][1]) rs[mt][1] += e2;
                    if (c1t != rtk[mt][1]) rs[mt][1] += e3;
                }
        }

        // lane-group reduce, then the wx pair via smem
#pragma unroll
        for (int mt = 0; mt < 2; mt++)
#pragma unroll
            for (int h = 0; h < 2; h++) {
                rs[mt][h] += __shfl_xor_sync(0xffffffffu, rs[mt][h], 1);
                rs[mt][h] += __shfl_xor_sync(0xffffffffu, rs[mt][h], 2);
            }
        if ((lane & 3) == 0) {
#pragma unroll
            for (int mt = 0; mt < 2; mt++)
#pragma unroll
                for (int h = 0; h < 2; h++) {
                    int rl = wy * 32 + mt * 16 + (lane >> 2) + h * 8;
                    red[rl * 2 + wx] = rs[mt][h];
                }
        }
        __syncthreads();
        if (tid < 128)
            atomicAdd(&g_den[rb * 128 + tid], red[tid * 2] + red[tid * 2 + 1]);
        __syncthreads();      // red + B[buf] (+ A on migration) free

        if (nxt >= 0 && !pre) {       // rb migration: reload A + B
            int nrb = nxt >> 6, nct = nxt & 63;
            if (tid == 0) {
                mbar_expect_tx(mbA, TILE_BYTES);
                bulk_g2s(sb + SM_A, gA + (size_t)nrb * TILE_BYTES, TILE_BYTES, mbA);
                uint32_t mb = buf ? mbB0 : mbB1;
                mbar_expect_tx(mb, TILE_BYTES);
                bulk_g2s(sb + SM_B0 + (uint32_t)(buf ^ 1) * TILE_BYTES,
                         gB + (size_t)nct * TILE_BYTES, TILE_BYTES, mb);
            }
            if (nct >= 32 && tid < 128)
                cts[(buf ^ 1) * 128 + tid] = __ldg(&tidx[nct * 128 + tid - N]);
            loadedA = nrb;
            A_pending = true;
        }
        cur = nxt;
        buf ^= 1;
        if (tid == 0) ctrl[0] = (cur >= 0) ? acq() : -1;
        __syncthreads();
        nxt = ctrl[0];
    }

    // finish: last CTA resets tickets for the next graph replay
    if (tid == 0) {
        __threadfence();
        unsigned old = atomicInc(&g_done, NUM_CTA - 1u);  // wraps to 0 on 296th
        if (old == NUM_CTA - 1u) {
#pragma unroll
            for (int i = 0; i < NUM_RB; i++) g_tick[i] = 0;
        }
    }
}

// ---------------------------------------------------------------------------
// kC: per-block partial of sum_{i in 16-row chunk, all j} log(den[j]+num[i])
//     minus N*sum lognum[i]; last block reduces and writes the output.
// ---------------------------------------------------------------------------
__global__ void kC(float* out) {
    __shared__ double dred[256];
    __shared__ unsigned isLast;
    int tid = threadIdx.x;
    int i0  = blockIdx.x * 16;
    float nums[16];
#pragma unroll
    for (int ii = 0; ii < 16; ii++) nums[ii] = g_num[i0 + ii];
    double dpart = 0.0;
    for (int j = tid; j < N; j += 256) {
        float dj = __ldg(&g_den[j]);
        float s  = 0.0f;
#pragma unroll
        for (int ii = 0; ii < 16; ii++) s += __logf(dj + nums[ii]);
        dpart += (double)s;
    }
    dred[tid] = dpart;
    __syncthreads();
    for (int off = 128; off > 0; off >>= 1) {
        if (tid < off) dred[tid] += dred[tid + off];
        __syncthreads();
    }
    if (tid == 0) {
        double ln = 0.0;
#pragma unroll
        for (int ii = 0; ii < 16; ii++) ln += (double)g_lognum[i0 + ii];
        g_lossp[blockIdx.x] = dred[0] - (double)N * ln;
        __threadfence();
        unsigned old = atomicInc(&g_kc_done, 255u);   // wraps to 0 on 256th
        isLast = (old == 255u);
    }
    __syncthreads();
    if (isLast) {
        dred[tid] = g_lossp[tid];
        __syncthreads();
        for (int off = 128; off > 0; off >>= 1) {
            if (tid < off) dred[tid] += dred[tid + off];
            __syncthreads();
        }
        if (tid == 0) out[0] = (float)(dred[0] / ((double)N * (double)N));
    }
}

// ---------------------------------------------------------------------------
extern "C" void kernel_launch(void* const* d_in, const int* in_sizes, int n_in,
                              void* d_out, int out_size) {
    const float* x    = (const float*)d_in[0];
    const int*   tidx = (const int*)  d_in[1];
    const float* y    = (const float*)d_in[2];
    float*       out  = (float*)d_out;

    cudaFuncSetAttribute(kB, cudaFuncAttributeMaxDynamicSharedMemorySize, SMEM_BYTES);

    K1<<<1024, 256>>>(x, tidx, y);
    kB<<<NUM_CTA, 256, SMEM_BYTES>>>(tidx);
    kC<<<256, 256>>>(out);
}

// round 12
// speedup vs baseline: 1.2754x; 1.2754x over previous
#include <cuda_runtime.h>
#include <cuda_fp16.h>
#include <math_constants.h>
#include <cstdint>
#include <cstring>

#define N 4096
#define D 128
#define NT 512
#define Q 8
#define NCOL 8192
#define INV_TEMP 20.0f
#define EX2_SCALE 28.85390081777927f   // 20 * log2(e)
#define TILE_BYTES 32768

// ---------------------------------------------------------------------------
// Device scratch (no allocation allowed)
// ---------------------------------------------------------------------------
__device__ float  g_num[N];
__device__ float  g_lognum[N];
__device__ float  g_den[N];
__device__ double g_lossp[256];
__device__ unsigned g_kc_done;          // self-resetting last-block ticket
// concat(yf, x) fp16, TILE-MAJOR SWIZZLED: tile tl = bytes [tl*32768,(tl+1)*32768)
// element (row r, 16B-unit c8): off = r*256 + ((c8 ^ (r&7)) << 4)
__device__ __align__(128) __half g_Bh[NCOL * D];
// x rows prescaled by EX2_SCALE (row/A operand only), same tiled layout, 32 tiles
__device__ __align__(128) __half g_Ah[N * D];

// ---------------------------------------------------------------------------
// Helpers (base ISA; cp.async.bulk/mbarrier are sm_90 base features)
// ---------------------------------------------------------------------------
__device__ __forceinline__ uint32_t smem_u32(const void* p) {
    uint32_t a;
    asm("{ .reg .u64 t; cvta.to.shared.u64 t, %1; cvt.u32.u64 %0, t; }"
        : "=r"(a) : "l"(p));
    return a;
}
__device__ __forceinline__ void mbar_init(uint32_t addr, uint32_t cnt) {
    asm volatile("mbarrier.init.shared.b64 [%0], %1;" :: "r"(addr), "r"(cnt) : "memory");
}
__device__ __forceinline__ void mbar_expect_tx(uint32_t addr, uint32_t tx) {
    asm volatile("mbarrier.arrive.expect_tx.shared.b64 _, [%0], %1;"
                 :: "r"(addr), "r"(tx) : "memory");
}
__device__ __forceinline__ void mbar_wait(uint32_t addr, uint32_t parity) {
    asm volatile(
        "{\n\t.reg .pred P;\n\t"
        "LW_%=:\n\t"
        "mbarrier.try_wait.parity.shared.b64 P, [%0], %1;\n\t"
        "@P bra LD_%=;\n\t"
        "bra LW_%=;\n\t"
        "LD_%=:\n\t}"
        :: "r"(addr), "r"(parity) : "memory");
}
__device__ __forceinline__ void bulk_g2s(uint32_t dst, const void* src,
                                         uint32_t bytes, uint32_t mbar) {
    asm volatile(
        "cp.async.bulk.shared::cluster.global.mbarrier::complete_tx::bytes "
        "[%0], [%1], %2, [%3];"
        :: "r"(dst), "l"(src), "r"(bytes), "r"(mbar) : "memory");
}
__device__ __forceinline__ void ldsm4(uint32_t* v, uint32_t addr) {
    asm volatile("ldmatrix.sync.aligned.m8n8.x4.shared.b16 {%0,%1,%2,%3}, [%4];"
                 : "=r"(v[0]), "=r"(v[1]), "=r"(v[2]), "=r"(v[3]) : "r"(addr));
}
__device__ __forceinline__ void mma16816(float* c, const uint32_t* a, const uint32_t* b) {
    asm volatile(
        "mma.sync.aligned.m16n8k16.row.col.f32.f16.f16.f32 "
        "{%0,%1,%2,%3}, {%4,%5,%6,%7}, {%8,%9}, {%0,%1,%2,%3};"
        : "+f"(c[0]), "+f"(c[1]), "+f"(c[2]), "+f"(c[3])
        : "r"(a[0]), "r"(a[1]), "r"(a[2]), "r"(a[3]), "r"(b[0]), "r"(b[1]));
}
__device__ __forceinline__ float ex2f(float x) {
    float r;
    asm("ex2.approx.f32 %0, %1;" : "=f"(r) : "f"(x));
    return r;
}

// ---------------------------------------------------------------------------
// SMEM layout for kB (per CTA; 2 CTAs/SM)
// ---------------------------------------------------------------------------
#define SM_A    0                   // 32768
#define SM_B0   32768               // + buf*32768
#define SM_CTS  98304               // int cts[2][128] = 1024
#define SM_RED  99328               // float red[128][2] = 1024
#define SM_MBAR 100352              // 2 mbarriers, 16 B
#define SMEM_BYTES 100480

// ---------------------------------------------------------------------------
// K1: fused prep.
//   blocks [0, 512):    convert concat(yf, x) -> fp16 tiled/swizzled (+ scaled A copy)
//   blocks [512, 1024): per-row sim_p/num/lognum (exact fp32), zero g_den
// ---------------------------------------------------------------------------
__global__ void K1(const float* __restrict__ x,
                   const int*   __restrict__ tidx,
                   const float* __restrict__ y) {
    int bid = blockIdx.x;
    int tid = threadIdx.x;
    if (bid < 512) {
        int uid = bid * 256 + tid;          // 131072 16B-units
        int R   = uid >> 4;                 // concat row
        int c8  = uid & 15;
        int tl  = R >> 7;
        int r   = R & 127;
        const float4* rowp = (R < N) ? ((const float4*)y + (size_t)R * (D / 4))
                                     : ((const float4*)x + (size_t)(R - N) * (D / 4));
        float4 f0 = rowp[c8 * 2];
        float4 f1 = rowp[c8 * 2 + 1];
        uint32_t off = (uint32_t)r * 256 + ((uint32_t)(c8 ^ (r & 7)) << 4);
        {
            __half2 hh[4];
            hh[0] = __floats2half2_rn(f0.x, f0.y);
            hh[1] = __floats2half2_rn(f0.z, f0.w);
            hh[2] = __floats2half2_rn(f1.x, f1.y);
            hh[3] = __floats2half2_rn(f1.z, f1.w);
            uint4 o; memcpy(&o, hh, 16);
            *(uint4*)((char*)g_Bh + (uint32_t)tl * TILE_BYTES + off) = o;
        }
        if (R >= N) {                       // prescaled A copy (x rows only)
            __half2 hs[4];
            hs[0] = __floats2half2_rn(f0.x * EX2_SCALE, f0.y * EX2_SCALE);
            hs[1] = __floats2half2_rn(f0.z * EX2_SCALE, f0.w * EX2_SCALE);
            hs[2] = __floats2half2_rn(f1.x * EX2_SCALE, f1.y * EX2_SCALE);
            hs[3] = __floats2half2_rn(f1.z * EX2_SCALE, f1.w * EX2_SCALE);
            uint4 o; memcpy(&o, hs, 16);
            *(uint4*)((char*)g_Ah + (uint32_t)(tl - 32) * TILE_BYTES + off) = o;
        }
    } else {
        int gw   = (bid - 512) * 8 + (tid >> 5);
        int lane = tid & 31;
        const float* xr = x + (size_t)gw * D;
        float x0 = xr[lane], x1 = xr[lane + 32], x2 = xr[lane + 64], x3 = xr[lane + 96];
        const float* yb = y + (size_t)tidx[gw] * Q * D;
        float mn = CUDART_INF_F;
#pragma unroll
        for (int q = 0; q < Q; q++) {
            const float* yr = yb + q * D;
            float s = x0 * yr[lane] + x1 * yr[lane + 32]
                    + x2 * yr[lane + 64] + x3 * yr[lane + 96];
#pragma unroll
            for (int o = 16; o > 0; o >>= 1) s += __shfl_xor_sync(0xffffffffu, s, o);
            mn = fminf(mn, s);
        }
        if (lane == 0) {
            float lognum = mn * INV_TEMP;
            g_num[gw]    = __expf(lognum);
            g_lognum[gw] = lognum;
            g_den[gw]    = 0.0f;
        }
    }
}

// ---------------------------------------------------------------------------
// kB: fp16 masked-exp GEMM row-sum, bulk-copy fed, prescaled A (acc = 28.85*S).
//   grid (16, 32): blockIdx.y = 128-row block, blockIdx.x = 4-col-tile chunk.
//   blockIdx.x < 8  -> y-half columns (track = col>>3, ALU only)
//   256 threads, 8 warps (4x2), warp tile 32x64, full K=128, 2 CTAs/SM.
// ---------------------------------------------------------------------------
__global__ __launch_bounds__(256, 2)
void kB(const int* __restrict__ tidx) {
    extern __shared__ char smem[];
    const uint32_t sb = smem_u32(smem);
    const int tid  = threadIdx.x;
    const int lane = tid & 31;
    const int wrp  = tid >> 5;
    const int wy   = wrp >> 1;            // 0..3  (32-row slab)
    const int wx   = wrp & 1;             // 0..1  (64-col slab)
    const int rb   = blockIdx.y;
    const int t0   = blockIdx.x * 4;
    const bool is_y = (blockIdx.x < 8);

    int*   cts = (int*)  (smem + SM_CTS);
    float* red = (float*)(smem + SM_RED);
    const uint32_t mb0 = sb + SM_MBAR;
    const uint32_t mb1 = sb + SM_MBAR + 8;
    const char* gB = (const char*)g_Bh;

    if (tid == 0) { mbar_init(mb0, 1); mbar_init(mb1, 1); }
    __syncthreads();

    // Preload: A + B(t0) on mb0 (tx=2 tiles), B(t0+1) on mb1.
    if (tid == 0) {
        mbar_expect_tx(mb0, 2 * TILE_BYTES);
        bulk_g2s(sb + SM_A,  (const char*)g_Ah + (size_t)rb * TILE_BYTES,
                 TILE_BYTES, mb0);
        bulk_g2s(sb + SM_B0, gB + (size_t)t0 * TILE_BYTES,        TILE_BYTES, mb0);
        mbar_expect_tx(mb1, TILE_BYTES);
        bulk_g2s(sb + SM_B0 + TILE_BYTES, gB + (size_t)(t0 + 1) * TILE_BYTES,
                 TILE_BYTES, mb1);
    }
    if (!is_y && tid < 128) {
        cts[tid]       = __ldg(&tidx[t0 * 128 + tid - N]);
        cts[128 + tid] = __ldg(&tidx[(t0 + 1) * 128 + tid - N]);
    }

    // Row tracks for this thread's 4 output rows
    int rtk[2][2];
#pragma unroll
    for (int mt = 0; mt < 2; mt++)
#pragma unroll
        for (int h = 0; h < 2; h++) {
            int rl = wy * 32 + mt * 16 + (lane >> 2) + h * 8;
            rtk[mt][h] = __ldg(&tidx[rb * 128 + rl]);
        }

    // ldmatrix per-lane address precompute
    const int lr = lane & 7, g = lane >> 3;
    uint32_t arow[2], ars[2], brow[4], brs[4];
#pragma unroll
    for (int mt = 0; mt < 2; mt++) {
        int r = wy * 32 + mt * 16 + (g & 1) * 8 + lr;
        arow[mt] = (uint32_t)(r * 256); ars[mt] = (uint32_t)(r & 7);
    }
    const uint32_t akb = (uint32_t)(g >> 1);
#pragma unroll
    for (int np = 0; np < 4; np++) {
        int r = wx * 64 + np * 16 + (g >> 1) * 8 + lr;
        brow[np] = (uint32_t)(r * 256); brs[np] = (uint32_t)(r & 7);
    }
    const uint32_t bkb = (uint32_t)(g & 1);

    float rs[2][2] = {{0.f, 0.f}, {0.f, 0.f}};
    __syncthreads();          // cts[0], cts[1] visible

    for (int t = 0; t < 4; t++) {
        const int buf = t & 1;
        const int ph  = (t >> 1) & 1;
        const int ct  = t0 + t;
        mbar_wait(buf ? mb1 : mb0, (uint32_t)ph);

        // ---- compute 128x128 tile, single fp16 product (A prescaled) ----
        float acc[2][8][4];
#pragma unroll
        for (int mt = 0; mt < 2; mt++)
#pragma unroll
            for (int nt = 0; nt < 8; nt++)
#pragma unroll
                for (int e = 0; e < 4; e++) acc[mt][nt][e] = 0.f;

        const uint32_t bcur = sb + SM_B0 + (uint32_t)buf * TILE_BYTES;
#pragma unroll
        for (int ks = 0; ks < 8; ks++) {
            uint32_t af[2][4];
#pragma unroll
            for (int mt = 0; mt < 2; mt++)
                ldsm4(af[mt], sb + SM_A + arow[mt]
                      + ((((uint32_t)(ks * 2) + akb) ^ ars[mt]) << 4));
            uint32_t bf[4][4];
#pragma unroll
            for (int np = 0; np < 4; np++)
                ldsm4(bf[np], bcur + brow[np]
                      + ((((uint32_t)(ks * 2) + bkb) ^ brs[np]) << 4));
#pragma unroll
            for (int mt = 0; mt < 2; mt++)
#pragma unroll
                for (int nt = 0; nt < 8; nt++)
                    mma16816(acc[mt][nt], af[mt], &bf[nt >> 1][(nt & 1) * 2]);
        }

        // ---- epilogue: mask same-track, bare ex2, per-row partials ----
        if (is_y) {
            int vbase = (ct * 128 + wx * 64 + (lane & 3) * 2) >> 3;
#pragma unroll
            for (int mt = 0; mt < 2; mt++)
#pragma unroll
                for (int nt = 0; nt < 8; nt++) {
                    int trk = vbase + nt;
                    float s01 = ex2f(acc[mt][nt][0]) + ex2f(acc[mt][nt][1]);
                    float s23 = ex2f(acc[mt][nt][2]) + ex2f(acc[mt][nt][3]);
                    if (trk != rtk[mt][0]) rs[mt][0] += s01;
                    if (trk != rtk[mt][1]) rs[mt][1] += s23;
                }
        } else {
            const int* ctc = cts + buf * 128;
#pragma unroll
            for (int mt = 0; mt < 2; mt++)
#pragma unroll
                for (int nt = 0; nt < 8; nt++) {
                    int colb = wx * 64 + nt * 8 + (lane & 3) * 2;
                    int c0t = ctc[colb], c1t = ctc[colb + 1];
                    float e0 = ex2f(acc[mt][nt][0]);
                    float e1 = ex2f(acc[mt][nt][1]);
                    float e2 = ex2f(acc[mt][nt][2]);
                    float e3 = ex2f(acc[mt][nt][3]);
                    if (c0t != rtk[mt][0]) rs[mt][0] += e0;
                    if (c1t != rtk[mt][0]) rs[mt][0] += e1;
                    if (c0t != rtk[mt][1]) rs[mt][1] += e2;
                    if (c1t != rtk[mt][1]) rs[mt][1] += e3;
                }
        }

        __syncthreads();      // all warps done with buf (smem + cts slot)
        if (t + 2 < 4) {
            if (tid == 0) {
                uint32_t mb = buf ? mb1 : mb0;
                mbar_expect_tx(mb, TILE_BYTES);
                bulk_g2s(sb + SM_B0 + (uint32_t)buf * TILE_BYTES,
                         gB + (size_t)(ct + 2) * TILE_BYTES, TILE_BYTES, mb);
            }
            if (!is_y && tid < 128)
                cts[buf * 128 + tid] = __ldg(&tidx[(ct + 2) * 128 + tid - N]);
        }
    }

    // ---- final reduction: lanes sharing a row, then the wx pair ----
#pragma unroll
    for (int mt = 0; mt < 2; mt++)
#pragma unroll
        for (int h = 0; h < 2; h++) {
            rs[mt][h] += __shfl_xor_sync(0xffffffffu, rs[mt][h], 1);
            rs[mt][h] += __shfl_xor_sync(0xffffffffu, rs[mt][h], 2);
        }
    if ((lane & 3) == 0) {
#pragma unroll
        for (int mt = 0; mt < 2; mt++)
#pragma unroll
            for (int h = 0; h < 2; h++) {
                int rl = wy * 32 + mt * 16 + (lane >> 2) + h * 8;
                red[rl * 2 + wx] = rs[mt][h];
            }
    }
    __syncthreads();
    if (tid < 128)
        atomicAdd(&g_den[rb * 128 + tid], red[tid * 2] + red[tid * 2 + 1]);
}

// ---------------------------------------------------------------------------
// kC: per-block partial of sum_{i in 16-row chunk, all j} log(den[j]+num[i])
//     minus N*sum lognum[i]; last block reduces and writes the output.
// ---------------------------------------------------------------------------
__global__ void kC(float* out) {
    __shared__ double dred[256];
    __shared__ unsigned isLast;
    int tid = threadIdx.x;
    int i0  = blockIdx.x * 16;
    float nums[16];
#pragma unroll
    for (int ii = 0; ii < 16; ii++) nums[ii] = g_num[i0 + ii];
    double dpart = 0.0;
    for (int j = tid; j < N; j += 256) {
        float dj = __ldg(&g_den[j]);
        float s  = 0.0f;
#pragma unroll
        for (int ii = 0; ii < 16; ii++) s += __logf(dj + nums[ii]);
        dpart += (double)s;
    }
    dred[tid] = dpart;
    __syncthreads();
    for (int off = 128; off > 0; off >>= 1) {
        if (tid < off) dred[tid] += dred[tid + off];
        __syncthreads();
    }
    if (tid == 0) {
        double ln = 0.0;
#pragma unroll
        for (int ii = 0; ii < 16; ii++) ln += (double)g_lognum[i0 + ii];
        g_lossp[blockIdx.x] = dred[0] - (double)N * ln;
        __threadfence();
        unsigned old = atomicInc(&g_kc_done, 255u);   // wraps to 0 on 256th
        isLast = (old == 255u);
    }
    __syncthreads();
    if (isLast) {
        dred[tid] = g_lossp[tid];
        __syncthreads();
        for (int off = 128; off > 0; off >>= 1) {
            if (tid < off) dred[tid] += dred[tid + off];
            __syncthreads();
        }
        if (tid == 0) out[0] = (float)(dred[0] / ((double)N * (double)N));
    }
}

// ---------------------------------------------------------------------------
extern "C" void kernel_launch(void* const* d_in, const int* in_sizes, int n_in,
                              void* d_out, int out_size) {
    const float* x    = (const float*)d_in[0];
    const int*   tidx = (const int*)  d_in[1];
    const float* y    = (const float*)d_in[2];
    float*       out  = (float*)d_out;

    cudaFuncSetAttribute(kB, cudaFuncAttributeMaxDynamicSharedMemorySize, SMEM_BYTES);

    K1<<<1024, 256>>>(x, tidx, y);
    dim3 gB(16, 32);
    kB<<<gB, 256, SMEM_BYTES>>>(tidx);
    kC<<<256, 256>>>(out);
}